// round 14
// baseline (speedup 1.0000x reference)
#include <cuda_runtime.h>
#include <cuda_fp16.h>
#include <cstdint>
#include <cstddef>

#define NROWS 200000
#define DIMX 256
#define HID 128
#define NSEG 512

constexpr int TILE_M = 128;
constexpr int NTILES = (NROWS + TILE_M - 1) / TILE_M;  // 1563
constexpr int TPB = 256;  // 8 warps: 4 mg x 2 ng

// ---- smem layout (bytes) ----
constexpr int SM_B1 = 0;           // float[128]
constexpr int SM_W2 = 512;         // float[128]
constexpr int SM_SPART = 1152;     // float[128][2]
constexpr int SM_WHI = 4096;       // 4 panels x 16KB (SW128, fp16)
constexpr int SM_A = SM_WHI + 65536;   // ring: 3 stages x 12288 B (128 rows x 24 floats)
constexpr int A_STAGE = 12288;
constexpr int SMEM_TOTAL = SM_A + 3 * A_STAGE;  // 106496 (104 KB) -> 2 CTAs/SM

__device__ float g_scores[NROWS];
__device__ unsigned int g_maxu[NSEG];
__device__ float g_den[NSEG];
__device__ __half g_wt[HID * DIMX];  // [n][k] fp16

// ---------------- helpers ----------------
__device__ __forceinline__ uint32_t smem_u32(const void *p) {
    uint32_t a;
    asm("{ .reg .u64 t; cvta.to.shared.u64 t, %1; cvt.u32.u64 %0, t; }" : "=r"(a) : "l"(p));
    return a;
}
#define SWZ(off) ((uint32_t)(off) ^ ((((uint32_t)(off)) >> 3) & 0x70u))

__device__ __forceinline__ uint32_t packh(float lo, float hi) {
    uint32_t r;
    asm("cvt.rn.f16x2.f32 %0, %1, %2;" : "=r"(r) : "f"(hi), "f"(lo));
    return r;
}
__device__ __forceinline__ float htanh(float x) {
    float r;
    asm("tanh.approx.f32 %0, %1;" : "=f"(r) : "f"(x));
    return r;
}
__device__ __forceinline__ uint32_t fenc(float f) {
    uint32_t b = __float_as_uint(f);
    return (b & 0x80000000u) ? ~b : (b | 0x80000000u);
}
__device__ __forceinline__ float fdec(uint32_t u) {
    return __uint_as_float((u & 0x80000000u) ? (u ^ 0x80000000u) : ~u);
}
__device__ __forceinline__ void cp16(uint32_t smem_dst, const void *gsrc) {
    asm volatile("cp.async.cg.shared.global [%0], [%1], 16;" ::"r"(smem_dst), "l"(gsrc));
}
__device__ __forceinline__ void cp_commit() { asm volatile("cp.async.commit_group;"); }
template <int N>
__device__ __forceinline__ void cp_wait() {
    asm volatile("cp.async.wait_group %0;" ::"n"(N));
}

__device__ __forceinline__ void ldsm4(uint32_t *r, uint32_t addr) {
    asm volatile("ldmatrix.sync.aligned.m8n8.x4.shared.b16 {%0,%1,%2,%3}, [%4];"
                 : "=r"(r[0]), "=r"(r[1]), "=r"(r[2]), "=r"(r[3]) : "r"(addr));
}
__device__ __forceinline__ void mma16816(float *d, const uint32_t *a, const uint32_t *b) {
    asm volatile("mma.sync.aligned.m16n8k16.row.col.f32.f16.f16.f32 "
                 "{%0,%1,%2,%3}, {%4,%5,%6,%7}, {%8,%9}, {%0,%1,%2,%3};"
                 : "+f"(d[0]), "+f"(d[1]), "+f"(d[2]), "+f"(d[3])
                 : "r"(a[0]), "r"(a[1]), "r"(a[2]), "r"(a[3]), "r"(b[0]), "r"(b[1]));
}

// ---------------- prep: W1 -> Wt fp16; init max/den ----------------
__global__ void prep_w(const float *__restrict__ W1) {
    int i = blockIdx.x * 256 + threadIdx.x;  // 32768
    int k = i >> 7, n = i & 127;             // W1[k][n]
    g_wt[n * DIMX + k] = __float2half_rn(W1[i]);
    if (i < NSEG) { g_maxu[i] = 0u; g_den[i] = 0.f; }
}

// ---------------- scores: fp16 1-term, cp.async ring, occ 2, pipelined tiles ----------------
__global__ void __launch_bounds__(TPB, 2)
scores_kernel(const float *__restrict__ x, const float *__restrict__ b1,
              const float *__restrict__ W2, const int *__restrict__ batch) {
    extern __shared__ char smem[];
    const uint32_t sb = smem_u32(smem);
    const int tid = threadIdx.x;
    const int wid = tid >> 5, lane = tid & 31;
    const int mg = wid >> 1, ng = wid & 1;  // rows 32*mg.., cols 64*ng..

    if (tid < HID) {
        ((float *)(smem + SM_B1))[tid] = b1[tid];
        ((float *)(smem + SM_W2))[tid] = W2[tid];
    }
    for (int i = tid; i < HID * (DIMX / 4); i += TPB) {
        int n = i >> 6, k4 = i & 63;
        uint2 vh = *(const uint2 *)(g_wt + n * DIMX + k4 * 4);
        uint32_t off = SWZ(n * 128 + (k4 & 15) * 8) + (uint32_t)(k4 >> 4) * 16384u;
        *(uint2 *)(smem + SM_WHI + off) = vh;
    }
    __syncthreads();

    float *spart = (float *)(smem + SM_SPART);
    const float *b1s = (const float *)(smem + SM_B1);
    const float *w2s = (const float *)(smem + SM_W2);

    const int lr = lane >> 2, cq = lane & 3;
    const int bn = ng * 64 + ((lane >> 4) & 1) * 8 + (lane & 7);
    const int bkb = ((lane >> 3) & 1) * 8;
    const int prow0 = (tid * 2) >> 2, pc40 = (tid * 2) & 3;
    const int prow1 = (tid * 2 + 1) >> 2, pc41 = (tid * 2 + 1) & 3;
    const uint32_t abase = sb + SM_A + (uint32_t)(mg * 32 + lr) * 96u + (uint32_t)cq * 8u;

    // loader: one k16-stage of tile starting at row tr0 into ring slot
    auto load_stage = [&](size_t tr0, int ksv, int slot) {
        size_t gr0 = min(tr0 + prow0, (size_t)(NROWS - 1));
        size_t gr1 = min(tr0 + prow1, (size_t)(NROWS - 1));
        cp16(sb + SM_A + slot * A_STAGE + prow0 * 96 + pc40 * 16,
             x + gr0 * 256 + ksv * 16 + pc40 * 4);
        cp16(sb + SM_A + slot * A_STAGE + prow1 * 96 + pc41 * 16,
             x + gr1 * 256 + ksv * 16 + pc41 * 4);
        cp_commit();
    };

    // prologue for first tile
    if (blockIdx.x < NTILES) {
        const size_t fr0 = (size_t)blockIdx.x * TILE_M;
        load_stage(fr0, 0, 0);
        load_stage(fr0, 1, 1);
    }

    for (int tile = blockIdx.x; tile < NTILES; tile += gridDim.x) {
        const size_t r0 = (size_t)tile * TILE_M;

        float acc[2][8][4];
        #pragma unroll
        for (int mt = 0; mt < 2; mt++)
            #pragma unroll
            for (int nt = 0; nt < 8; nt++) {
                int c0 = ng * 64 + nt * 8 + cq * 2;
                acc[mt][nt][0] = b1s[c0];
                acc[mt][nt][1] = b1s[c0 + 1];
                acc[mt][nt][2] = acc[mt][nt][0];
                acc[mt][nt][3] = acc[mt][nt][1];
            }

        #pragma unroll
        for (int ks = 0; ks < 16; ks++) {
            if (ks < 15) cp_wait<1>(); else cp_wait<0>();
            __syncthreads();
            if (ks + 2 < 16) load_stage(r0, ks + 2, (ks + 2) % 3);

            const uint32_t aslot = abase + (uint32_t)((ks % 3) * A_STAGE);
            uint32_t ah[2][4];
            #pragma unroll
            for (int mt = 0; mt < 2; mt++)
                #pragma unroll
                for (int j = 0; j < 4; j++) {
                    float2 v;
                    uint32_t addr = aslot + (uint32_t)((mt * 16 + (j & 1) * 8) * 96 + (j >> 1) * 32);
                    asm volatile("ld.shared.v2.f32 {%0,%1}, [%2];"
                                 : "=f"(v.x), "=f"(v.y) : "r"(addr));
                    ah[mt][j] = packh(v.x, v.y);
                }
            uint32_t bh[4][4];
            const uint32_t whp = sb + SM_WHI + (uint32_t)(ks >> 2) * 16384u;
            const int ki = (ks & 3) * 16 + bkb;
            #pragma unroll
            for (int nt2 = 0; nt2 < 4; nt2++) {
                uint32_t off = SWZ((bn + nt2 * 16) * 128 + ki * 2);
                ldsm4(bh[nt2], whp + off);
            }
            #pragma unroll
            for (int mt = 0; mt < 2; mt++)
                #pragma unroll
                for (int nt = 0; nt < 8; nt++)
                    mma16816(acc[mt][nt], ah[mt], &bh[nt >> 1][(nt & 1) * 2]);
        }

        // all ring reads done -> issue NEXT tile's prologue, overlapping the epilogue
        __syncthreads();
        {
            int ntile = tile + gridDim.x;
            if (ntile < NTILES) {
                const size_t nr0 = (size_t)ntile * TILE_M;
                load_stage(nr0, 0, 0);
                load_stage(nr0, 1, 1);
            }
        }

        // ---- epilogue: MUFU tanh + dot W2 ----
        #pragma unroll
        for (int mt = 0; mt < 2; mt++)
            #pragma unroll
            for (int qh = 0; qh < 2; qh++) {
                float p = 0.f;
                #pragma unroll
                for (int nt = 0; nt < 8; nt++) {
                    int c0 = ng * 64 + nt * 8 + cq * 2;
                    p += htanh(acc[mt][nt][qh * 2 + 0]) * w2s[c0] +
                         htanh(acc[mt][nt][qh * 2 + 1]) * w2s[c0 + 1];
                }
                p += __shfl_xor_sync(0xffffffffu, p, 1);
                p += __shfl_xor_sync(0xffffffffu, p, 2);
                if (cq == 0)
                    spart[(mg * 32 + mt * 16 + qh * 8 + lr) * 2 + ng] = p;
            }
        __syncthreads();
        if (tid < 128) {
            size_t row = r0 + tid;
            if (row < NROWS) {
                float sc = spart[tid * 2] + spart[tid * 2 + 1];
                g_scores[row] = sc;
                atomicMax(&g_maxu[batch[row]], fenc(sc));  // segment max inline
            }
        }
        __syncthreads();
    }
}

// ---------------- den: e=exp(s-max) in place + segmented atomicAdd + zero out ----------------
constexpr int RPB = 256;
constexpr int PBLK = (NROWS + RPB - 1) / RPB;  // 782

__global__ void __launch_bounds__(256)
den_kernel(const int *__restrict__ batch, float *__restrict__ out) {
    const int row = blockIdx.x * 256 + threadIdx.x;
    const int lane = threadIdx.x & 31;
    if (blockIdx.x < NSEG) out[(size_t)blockIdx.x * DIMX + threadIdx.x] = 0.0f;
    const bool valid = row < NROWS;
    const int g = batch[valid ? row : NROWS - 1];
    float e = 0.f;
    if (valid) {
        e = expf(g_scores[row] - fdec(g_maxu[g]));
        g_scores[row] = e;
    }
    float v = e;
    #pragma unroll
    for (int off = 1; off < 32; off <<= 1) {
        float vv = __shfl_down_sync(0xffffffffu, v, off);
        int gg = __shfl_down_sync(0xffffffffu, g, off);
        if (lane + off < 32 && gg == g) v += vv;
    }
    int gprev = __shfl_up_sync(0xffffffffu, g, 1);
    if ((lane == 0 || gprev != g) && v != 0.f) atomicAdd(&g_den[g], v);
}

// ---------------- pool2: float4 lanes, 4 row-groups, shared flush ----------------
__global__ void __launch_bounds__(256)
pool2_kernel(const float *__restrict__ x, const int *__restrict__ batch,
             float *__restrict__ out) {
    const int tid = threadIdx.x;
    const int rq = tid >> 6, cq = tid & 63;
    const int r0 = blockIdx.x * RPB;
    const int rend = min(r0 + RPB, NROWS);
    const int g0 = batch[r0], g1 = batch[rend - 1];
    __shared__ float4 red4[256];
    const float4 *x4 = (const float4 *)x;

    for (int g = g0; g <= g1; g++) {
        int lo = r0, hi = rend;
        while (lo < hi) { int mid = (lo + hi) >> 1; if (batch[mid] < g) lo = mid + 1; else hi = mid; }
        const int s = lo;
        lo = r0; hi = rend;
        while (lo < hi) { int mid = (lo + hi) >> 1; if (batch[mid] < g + 1) lo = mid + 1; else hi = mid; }
        const int e = lo;
        if (s < e) {
            float4 acc = make_float4(0.f, 0.f, 0.f, 0.f);
            int r = s + rq;
            #pragma unroll 2
            for (; r + 4 < e; r += 8) {
                float w0 = g_scores[r];
                float4 v0 = x4[(size_t)r * 64 + cq];
                float w1 = g_scores[r + 4];
                float4 v1 = x4[(size_t)(r + 4) * 64 + cq];
                acc.x = fmaf(w0, v0.x, acc.x); acc.y = fmaf(w0, v0.y, acc.y);
                acc.z = fmaf(w0, v0.z, acc.z); acc.w = fmaf(w0, v0.w, acc.w);
                acc.x = fmaf(w1, v1.x, acc.x); acc.y = fmaf(w1, v1.y, acc.y);
                acc.z = fmaf(w1, v1.z, acc.z); acc.w = fmaf(w1, v1.w, acc.w);
            }
            if (r < e) {
                float w0 = g_scores[r];
                float4 v0 = x4[(size_t)r * 64 + cq];
                acc.x = fmaf(w0, v0.x, acc.x); acc.y = fmaf(w0, v0.y, acc.y);
                acc.z = fmaf(w0, v0.z, acc.z); acc.w = fmaf(w0, v0.w, acc.w);
            }
            red4[tid] = acc;
            __syncthreads();
            if (rq == 0) {
                const float inv = 1.0f / g_den[g];
                float4 a = red4[tid], b = red4[tid + 64];
                float4 c = red4[tid + 128], d = red4[tid + 192];
                a.x += b.x + c.x + d.x; a.y += b.y + c.y + d.y;
                a.z += b.z + c.z + d.z; a.w += b.w + c.w + d.w;
                float *op = out + (size_t)g * DIMX + cq * 4;
                atomicAdd(op + 0, a.x * inv);
                atomicAdd(op + 1, a.y * inv);
                atomicAdd(op + 2, a.z * inv);
                atomicAdd(op + 3, a.w * inv);
            }
            __syncthreads();
        }
    }
}

// ---------------- launch ----------------
extern "C" void kernel_launch(void *const *d_in, const int *in_sizes, int n_in,
                              void *d_out, int out_size) {
    (void)in_sizes; (void)n_in; (void)out_size;
    const float *x = (const float *)d_in[0];
    const int *batch = (const int *)d_in[1];
    const float *W1 = (const float *)d_in[2];
    const float *b1 = (const float *)d_in[3];
    const float *W2 = (const float *)d_in[4];
    float *out = (float *)d_out;

    static int grid_s = 0;
    if (grid_s == 0) {
        int sm = 148;
        cudaDeviceGetAttribute(&sm, cudaDevAttrMultiProcessorCount, 0);
        grid_s = 2 * sm;
        cudaFuncSetAttribute(scores_kernel, cudaFuncAttributeMaxDynamicSharedMemorySize,
                             SMEM_TOTAL);
    }
    prep_w<<<HID * DIMX / 256, 256>>>(W1);
    scores_kernel<<<grid_s, TPB, SMEM_TOTAL>>>(x, b1, W2, batch);
    den_kernel<<<PBLK, 256>>>(batch, out);
    pool2_kernel<<<PBLK, 256>>>(x, batch, out);
}

// round 15
// speedup vs baseline: 1.3579x; 1.3579x over previous
#include <cuda_runtime.h>
#include <cuda_fp16.h>
#include <cstdint>
#include <cstddef>

#define NROWS 200000
#define DIMX 256
#define HID 128
#define NSEG 512

constexpr int TILE_M = 128;
constexpr int NTILES = (NROWS + TILE_M - 1) / TILE_M;  // 1563
constexpr int TPB = 256;  // 8 warps: 4 mg x 2 ng

// ---- smem layout (bytes) ----
constexpr int SM_B1 = 0;           // float[128]
constexpr int SM_W2 = 512;         // float[128]
constexpr int SM_SPART = 1152;     // float[128][2]
constexpr int SM_WHI = 4096;       // 4 panels x 16KB (SW128, fp16)
constexpr int SM_A = SM_WHI + 65536;   // ring: 3 stages x 12288 B (128 rows x 24 floats)
constexpr int A_STAGE = 12288;
constexpr int SMEM_TOTAL = SM_A + 3 * A_STAGE;  // 106496 (104 KB) -> 2 CTAs/SM

__device__ float g_scores[NROWS];
__device__ unsigned int g_maxu[NSEG];
__device__ float g_den[NSEG];
__device__ __half g_wt[HID * DIMX];  // [n][k] fp16

// ---------------- helpers ----------------
__device__ __forceinline__ uint32_t smem_u32(const void *p) {
    uint32_t a;
    asm("{ .reg .u64 t; cvta.to.shared.u64 t, %1; cvt.u32.u64 %0, t; }" : "=r"(a) : "l"(p));
    return a;
}
#define SWZ(off) ((uint32_t)(off) ^ ((((uint32_t)(off)) >> 3) & 0x70u))

__device__ __forceinline__ uint32_t packh(float lo, float hi) {
    uint32_t r;
    asm("cvt.rn.f16x2.f32 %0, %1, %2;" : "=r"(r) : "f"(hi), "f"(lo));
    return r;
}
__device__ __forceinline__ float htanh(float x) {
    float r;
    asm("tanh.approx.f32 %0, %1;" : "=f"(r) : "f"(x));
    return r;
}
__device__ __forceinline__ uint32_t fenc(float f) {
    uint32_t b = __float_as_uint(f);
    return (b & 0x80000000u) ? ~b : (b | 0x80000000u);
}
__device__ __forceinline__ float fdec(uint32_t u) {
    return __uint_as_float((u & 0x80000000u) ? (u ^ 0x80000000u) : ~u);
}
__device__ __forceinline__ void cp16(uint32_t smem_dst, const void *gsrc) {
    asm volatile("cp.async.cg.shared.global [%0], [%1], 16;" ::"r"(smem_dst), "l"(gsrc));
}
__device__ __forceinline__ void cp_commit() { asm volatile("cp.async.commit_group;"); }
template <int N>
__device__ __forceinline__ void cp_wait() {
    asm volatile("cp.async.wait_group %0;" ::"n"(N));
}

__device__ __forceinline__ void ldsm4(uint32_t *r, uint32_t addr) {
    asm volatile("ldmatrix.sync.aligned.m8n8.x4.shared.b16 {%0,%1,%2,%3}, [%4];"
                 : "=r"(r[0]), "=r"(r[1]), "=r"(r[2]), "=r"(r[3]) : "r"(addr));
}
__device__ __forceinline__ void mma16816(float *d, const uint32_t *a, const uint32_t *b) {
    asm volatile("mma.sync.aligned.m16n8k16.row.col.f32.f16.f16.f32 "
                 "{%0,%1,%2,%3}, {%4,%5,%6,%7}, {%8,%9}, {%0,%1,%2,%3};"
                 : "+f"(d[0]), "+f"(d[1]), "+f"(d[2]), "+f"(d[3])
                 : "r"(a[0]), "r"(a[1]), "r"(a[2]), "r"(a[3]), "r"(b[0]), "r"(b[1]));
}

// ---------------- prep: W1 -> Wt fp16; init max/den ----------------
__global__ void prep_w(const float *__restrict__ W1) {
    int i = blockIdx.x * 256 + threadIdx.x;  // 32768
    int k = i >> 7, n = i & 127;             // W1[k][n]
    g_wt[n * DIMX + k] = __float2half_rn(W1[i]);
    if (i < NSEG) { g_maxu[i] = 0u; g_den[i] = 0.f; }
}

// ---------------- scores: fp16 1-term, cp.async ring, occ 2, pipelined tiles ----------------
__global__ void __launch_bounds__(TPB, 2)
scores_kernel(const float *__restrict__ x, const float *__restrict__ b1,
              const float *__restrict__ W2, const int *__restrict__ batch) {
    extern __shared__ char smem[];
    const uint32_t sb = smem_u32(smem);
    const int tid = threadIdx.x;
    const int wid = tid >> 5, lane = tid & 31;
    const int mg = wid >> 1, ng = wid & 1;  // rows 32*mg.., cols 64*ng..

    if (tid < HID) {
        ((float *)(smem + SM_B1))[tid] = b1[tid];
        ((float *)(smem + SM_W2))[tid] = W2[tid];
    }
    for (int i = tid; i < HID * (DIMX / 4); i += TPB) {
        int n = i >> 6, k4 = i & 63;
        uint2 vh = *(const uint2 *)(g_wt + n * DIMX + k4 * 4);
        uint32_t off = SWZ(n * 128 + (k4 & 15) * 8) + (uint32_t)(k4 >> 4) * 16384u;
        *(uint2 *)(smem + SM_WHI + off) = vh;
    }
    __syncthreads();

    float *spart = (float *)(smem + SM_SPART);
    const float *b1s = (const float *)(smem + SM_B1);
    const float *w2s = (const float *)(smem + SM_W2);

    const int lr = lane >> 2, cq = lane & 3;
    const int bn = ng * 64 + ((lane >> 4) & 1) * 8 + (lane & 7);
    const int bkb = ((lane >> 3) & 1) * 8;
    const int prow0 = (tid * 2) >> 2, pc40 = (tid * 2) & 3;
    const int prow1 = (tid * 2 + 1) >> 2, pc41 = (tid * 2 + 1) & 3;
    const uint32_t abase = sb + SM_A + (uint32_t)(mg * 32 + lr) * 96u + (uint32_t)cq * 8u;

    auto load_stage = [&](size_t tr0, int ksv, int slot) {
        size_t gr0 = min(tr0 + prow0, (size_t)(NROWS - 1));
        size_t gr1 = min(tr0 + prow1, (size_t)(NROWS - 1));
        cp16(sb + SM_A + slot * A_STAGE + prow0 * 96 + pc40 * 16,
             x + gr0 * 256 + ksv * 16 + pc40 * 4);
        cp16(sb + SM_A + slot * A_STAGE + prow1 * 96 + pc41 * 16,
             x + gr1 * 256 + ksv * 16 + pc41 * 4);
        cp_commit();
    };

    // prologue for first tile
    if (blockIdx.x < NTILES) {
        const size_t fr0 = (size_t)blockIdx.x * TILE_M;
        load_stage(fr0, 0, 0);
        load_stage(fr0, 1, 1);
    }

    for (int tile = blockIdx.x; tile < NTILES; tile += gridDim.x) {
        const size_t r0 = (size_t)tile * TILE_M;

        float acc[2][8][4];
        #pragma unroll
        for (int mt = 0; mt < 2; mt++)
            #pragma unroll
            for (int nt = 0; nt < 8; nt++) {
                int c0 = ng * 64 + nt * 8 + cq * 2;
                acc[mt][nt][0] = b1s[c0];
                acc[mt][nt][1] = b1s[c0 + 1];
                acc[mt][nt][2] = acc[mt][nt][0];
                acc[mt][nt][3] = acc[mt][nt][1];
            }

        #pragma unroll
        for (int ks = 0; ks < 16; ks++) {
            if (ks < 15) cp_wait<1>(); else cp_wait<0>();
            __syncthreads();
            if (ks + 2 < 16) load_stage(r0, ks + 2, (ks + 2) % 3);

            const uint32_t aslot = abase + (uint32_t)((ks % 3) * A_STAGE);
            uint32_t ah[2][4];
            #pragma unroll
            for (int mt = 0; mt < 2; mt++)
                #pragma unroll
                for (int j = 0; j < 4; j++) {
                    float2 v;
                    uint32_t addr = aslot + (uint32_t)((mt * 16 + (j & 1) * 8) * 96 + (j >> 1) * 32);
                    asm volatile("ld.shared.v2.f32 {%0,%1}, [%2];"
                                 : "=f"(v.x), "=f"(v.y) : "r"(addr));
                    ah[mt][j] = packh(v.x, v.y);
                }
            uint32_t bh[4][4];
            const uint32_t whp = sb + SM_WHI + (uint32_t)(ks >> 2) * 16384u;
            const int ki = (ks & 3) * 16 + bkb;
            #pragma unroll
            for (int nt2 = 0; nt2 < 4; nt2++) {
                uint32_t off = SWZ((bn + nt2 * 16) * 128 + ki * 2);
                ldsm4(bh[nt2], whp + off);
            }
            #pragma unroll
            for (int mt = 0; mt < 2; mt++)
                #pragma unroll
                for (int nt = 0; nt < 8; nt++)
                    mma16816(acc[mt][nt], ah[mt], &bh[nt >> 1][(nt & 1) * 2]);
        }

        // ring reads done -> issue NEXT tile's prologue, overlapping epilogue
        __syncthreads();
        {
            int ntile = tile + gridDim.x;
            if (ntile < NTILES) {
                const size_t nr0 = (size_t)ntile * TILE_M;
                load_stage(nr0, 0, 0);
                load_stage(nr0, 1, 1);
            }
        }

        // ---- epilogue: MUFU tanh + dot W2 ----
        #pragma unroll
        for (int mt = 0; mt < 2; mt++)
            #pragma unroll
            for (int qh = 0; qh < 2; qh++) {
                float p = 0.f;
                #pragma unroll
                for (int nt = 0; nt < 8; nt++) {
                    int c0 = ng * 64 + nt * 8 + cq * 2;
                    p += htanh(acc[mt][nt][qh * 2 + 0]) * w2s[c0] +
                         htanh(acc[mt][nt][qh * 2 + 1]) * w2s[c0 + 1];
                }
                p += __shfl_xor_sync(0xffffffffu, p, 1);
                p += __shfl_xor_sync(0xffffffffu, p, 2);
                if (cq == 0)
                    spart[(mg * 32 + mt * 16 + qh * 8 + lr) * 2 + ng] = p;
            }
        __syncthreads();
        if (tid < 128) {
            size_t row = r0 + tid;
            const bool valid = row < NROWS;
            const int g = batch[valid ? row : NROWS - 1];
            float sc = -3.4e38f;
            if (valid) {
                sc = spart[tid * 2] + spart[tid * 2 + 1];
                g_scores[row] = sc;
            }
            // warp-segmented max over consecutive rows -> few atomics per tile
            float v = sc;
            #pragma unroll
            for (int off = 1; off < 32; off <<= 1) {
                float vv = __shfl_down_sync(0xffffffffu, v, off);
                int gg = __shfl_down_sync(0xffffffffu, g, off);
                if ((tid & 31) + off < 32 && gg == g) v = fmaxf(v, vv);
            }
            int gprev = __shfl_up_sync(0xffffffffu, g, 1);
            if (valid && ((tid & 31) == 0 || gprev != g)) atomicMax(&g_maxu[g], fenc(v));
        }
        __syncthreads();
    }
}

// ---------------- den: e=exp(s-max) in place + segmented atomicAdd + zero out ----------------
constexpr int RPB = 256;
constexpr int PBLK = (NROWS + RPB - 1) / RPB;  // 782

__global__ void __launch_bounds__(256)
den_kernel(const int *__restrict__ batch, float *__restrict__ out) {
    const int row = blockIdx.x * 256 + threadIdx.x;
    const int lane = threadIdx.x & 31;
    if (blockIdx.x < NSEG) out[(size_t)blockIdx.x * DIMX + threadIdx.x] = 0.0f;
    const bool valid = row < NROWS;
    const int g = batch[valid ? row : NROWS - 1];
    float e = 0.f;
    if (valid) {
        e = expf(g_scores[row] - fdec(g_maxu[g]));
        g_scores[row] = e;
    }
    float v = e;
    #pragma unroll
    for (int off = 1; off < 32; off <<= 1) {
        float vv = __shfl_down_sync(0xffffffffu, v, off);
        int gg = __shfl_down_sync(0xffffffffu, g, off);
        if (lane + off < 32 && gg == g) v += vv;
    }
    int gprev = __shfl_up_sync(0xffffffffu, g, 1);
    if ((lane == 0 || gprev != g) && v != 0.f) atomicAdd(&g_den[g], v);
}

// ---------------- pool2: float4 lanes, 4 row-groups, unroll-4, shared flush ----------------
__global__ void __launch_bounds__(256)
pool2_kernel(const float *__restrict__ x, const int *__restrict__ batch,
             float *__restrict__ out) {
    const int tid = threadIdx.x;
    const int rq = tid >> 6, cq = tid & 63;
    const int r0 = blockIdx.x * RPB;
    const int rend = min(r0 + RPB, NROWS);
    const int g0 = batch[r0], g1 = batch[rend - 1];
    __shared__ float4 red4[256];
    const float4 *x4 = (const float4 *)x;

    for (int g = g0; g <= g1; g++) {
        int lo = r0, hi = rend;
        while (lo < hi) { int mid = (lo + hi) >> 1; if (batch[mid] < g) lo = mid + 1; else hi = mid; }
        const int s = lo;
        lo = r0; hi = rend;
        while (lo < hi) { int mid = (lo + hi) >> 1; if (batch[mid] < g + 1) lo = mid + 1; else hi = mid; }
        const int e = lo;
        if (s < e) {
            float4 acc = make_float4(0.f, 0.f, 0.f, 0.f);
            int r = s + rq;
            // 4 rows in flight per thread: r, r+4, r+8, r+12 (all must be < e)
            for (; r + 12 < e; r += 16) {
                float w0 = g_scores[r];
                float4 v0 = x4[(size_t)r * 64 + cq];
                float w1 = g_scores[r + 4];
                float4 v1 = x4[(size_t)(r + 4) * 64 + cq];
                float w2 = g_scores[r + 8];
                float4 v2 = x4[(size_t)(r + 8) * 64 + cq];
                float w3 = g_scores[r + 12];
                float4 v3 = x4[(size_t)(r + 12) * 64 + cq];
                acc.x = fmaf(w0, v0.x, acc.x); acc.y = fmaf(w0, v0.y, acc.y);
                acc.z = fmaf(w0, v0.z, acc.z); acc.w = fmaf(w0, v0.w, acc.w);
                acc.x = fmaf(w1, v1.x, acc.x); acc.y = fmaf(w1, v1.y, acc.y);
                acc.z = fmaf(w1, v1.z, acc.z); acc.w = fmaf(w1, v1.w, acc.w);
                acc.x = fmaf(w2, v2.x, acc.x); acc.y = fmaf(w2, v2.y, acc.y);
                acc.z = fmaf(w2, v2.z, acc.z); acc.w = fmaf(w2, v2.w, acc.w);
                acc.x = fmaf(w3, v3.x, acc.x); acc.y = fmaf(w3, v3.y, acc.y);
                acc.z = fmaf(w3, v3.z, acc.z); acc.w = fmaf(w3, v3.w, acc.w);
            }
            for (; r < e; r += 4) {
                float w0 = g_scores[r];
                float4 v0 = x4[(size_t)r * 64 + cq];
                acc.x = fmaf(w0, v0.x, acc.x); acc.y = fmaf(w0, v0.y, acc.y);
                acc.z = fmaf(w0, v0.z, acc.z); acc.w = fmaf(w0, v0.w, acc.w);
            }
            red4[tid] = acc;
            __syncthreads();
            if (rq == 0) {
                const float inv = 1.0f / g_den[g];
                float4 a = red4[tid], b = red4[tid + 64];
                float4 c = red4[tid + 128], d = red4[tid + 192];
                a.x += b.x + c.x + d.x; a.y += b.y + c.y + d.y;
                a.z += b.z + c.z + d.z; a.w += b.w + c.w + d.w;
                float *op = out + (size_t)g * DIMX + cq * 4;
                atomicAdd(op + 0, a.x * inv);
                atomicAdd(op + 1, a.y * inv);
                atomicAdd(op + 2, a.z * inv);
                atomicAdd(op + 3, a.w * inv);
            }
            __syncthreads();
        }
    }
}

// ---------------- launch ----------------
extern "C" void kernel_launch(void *const *d_in, const int *in_sizes, int n_in,
                              void *d_out, int out_size) {
    (void)in_sizes; (void)n_in; (void)out_size;
    const float *x = (const float *)d_in[0];
    const int *batch = (const int *)d_in[1];
    const float *W1 = (const float *)d_in[2];
    const float *b1 = (const float *)d_in[3];
    const float *W2 = (const float *)d_in[4];
    float *out = (float *)d_out;

    static int grid_s = 0;
    if (grid_s == 0) {
        int sm = 148;
        cudaDeviceGetAttribute(&sm, cudaDevAttrMultiProcessorCount, 0);
        grid_s = 2 * sm;
        cudaFuncSetAttribute(scores_kernel, cudaFuncAttributeMaxDynamicSharedMemorySize,
                             SMEM_TOTAL);
    }
    prep_w<<<HID * DIMX / 256, 256>>>(W1);
    scores_kernel<<<grid_s, TPB, SMEM_TOTAL>>>(x, b1, W2, batch);
    den_kernel<<<PBLK, 256>>>(batch, out);
    pool2_kernel<<<PBLK, 256>>>(x, batch, out);
}

// round 16
// speedup vs baseline: 1.3823x; 1.0180x over previous
#include <cuda_runtime.h>
#include <cuda_fp16.h>
#include <cstdint>
#include <cstddef>

#define NROWS 200000
#define DIMX 256
#define HID 128
#define NSEG 512

constexpr int TILE_M = 128;
constexpr int NTILES = (NROWS + TILE_M - 1) / TILE_M;  // 1563
constexpr int TPB = 256;  // 8 warps: 4 mg x 2 ng

// ---- smem layout (bytes) ----
constexpr int SM_B1 = 0;           // float[128]
constexpr int SM_W2 = 512;         // float[128]
constexpr int SM_NEXT = 1024;      // int: next tile ticket
constexpr int SM_SPART = 1152;     // float[128][2]
constexpr int SM_WHI = 4096;       // 4 panels x 16KB (SW128, fp16)
constexpr int SM_A = SM_WHI + 65536;   // ring: 3 stages x 12288 B (128 rows x 24 floats)
constexpr int A_STAGE = 12288;
constexpr int SMEM_TOTAL = SM_A + 3 * A_STAGE;  // 106496 (104 KB) -> 2 CTAs/SM

__device__ float g_scores[NROWS];
__device__ unsigned int g_maxu[NSEG];
__device__ float g_den[NSEG];
__device__ __half g_wt[HID * DIMX];  // [n][k] fp16
__device__ int g_ticket;

// ---------------- helpers ----------------
__device__ __forceinline__ uint32_t smem_u32(const void *p) {
    uint32_t a;
    asm("{ .reg .u64 t; cvta.to.shared.u64 t, %1; cvt.u32.u64 %0, t; }" : "=r"(a) : "l"(p));
    return a;
}
#define SWZ(off) ((uint32_t)(off) ^ ((((uint32_t)(off)) >> 3) & 0x70u))

__device__ __forceinline__ uint32_t packh(float lo, float hi) {
    uint32_t r;
    asm("cvt.rn.f16x2.f32 %0, %1, %2;" : "=r"(r) : "f"(hi), "f"(lo));
    return r;
}
__device__ __forceinline__ float htanh(float x) {
    float r;
    asm("tanh.approx.f32 %0, %1;" : "=f"(r) : "f"(x));
    return r;
}
__device__ __forceinline__ uint32_t fenc(float f) {
    uint32_t b = __float_as_uint(f);
    return (b & 0x80000000u) ? ~b : (b | 0x80000000u);
}
__device__ __forceinline__ float fdec(uint32_t u) {
    return __uint_as_float((u & 0x80000000u) ? (u ^ 0x80000000u) : ~u);
}
__device__ __forceinline__ void cp16(uint32_t smem_dst, const void *gsrc) {
    asm volatile("cp.async.cg.shared.global [%0], [%1], 16;" ::"r"(smem_dst), "l"(gsrc));
}
__device__ __forceinline__ void cp_commit() { asm volatile("cp.async.commit_group;"); }
template <int N>
__device__ __forceinline__ void cp_wait() {
    asm volatile("cp.async.wait_group %0;" ::"n"(N));
}

__device__ __forceinline__ void ldsm4(uint32_t *r, uint32_t addr) {
    asm volatile("ldmatrix.sync.aligned.m8n8.x4.shared.b16 {%0,%1,%2,%3}, [%4];"
                 : "=r"(r[0]), "=r"(r[1]), "=r"(r[2]), "=r"(r[3]) : "r"(addr));
}
__device__ __forceinline__ void mma16816(float *d, const uint32_t *a, const uint32_t *b) {
    asm volatile("mma.sync.aligned.m16n8k16.row.col.f32.f16.f16.f32 "
                 "{%0,%1,%2,%3}, {%4,%5,%6,%7}, {%8,%9}, {%0,%1,%2,%3};"
                 : "+f"(d[0]), "+f"(d[1]), "+f"(d[2]), "+f"(d[3])
                 : "r"(a[0]), "r"(a[1]), "r"(a[2]), "r"(a[3]), "r"(b[0]), "r"(b[1]));
}

// ---------------- prep: W1 -> Wt fp16; init max/den/ticket ----------------
__global__ void prep_w(const float *__restrict__ W1, int ticket0) {
    int i = blockIdx.x * 256 + threadIdx.x;  // 32768
    int k = i >> 7, n = i & 127;             // W1[k][n]
    g_wt[n * DIMX + k] = __float2half_rn(W1[i]);
    if (i < NSEG) { g_maxu[i] = 0u; g_den[i] = 0.f; }
    if (i == 0) g_ticket = ticket0;
}

// ---------------- scores: fp16 1-term, cp.async ring, occ 2, dynamic tiles ----------------
__global__ void __launch_bounds__(TPB, 2)
scores_kernel(const float *__restrict__ x, const float *__restrict__ b1,
              const float *__restrict__ W2, const int *__restrict__ batch) {
    extern __shared__ char smem[];
    const uint32_t sb = smem_u32(smem);
    const int tid = threadIdx.x;
    const int wid = tid >> 5, lane = tid & 31;
    const int mg = wid >> 1, ng = wid & 1;  // rows 32*mg.., cols 64*ng..

    if (tid < HID) {
        ((float *)(smem + SM_B1))[tid] = b1[tid];
        ((float *)(smem + SM_W2))[tid] = W2[tid];
    }
    for (int i = tid; i < HID * (DIMX / 4); i += TPB) {
        int n = i >> 6, k4 = i & 63;
        uint2 vh = *(const uint2 *)(g_wt + n * DIMX + k4 * 4);
        uint32_t off = SWZ(n * 128 + (k4 & 15) * 8) + (uint32_t)(k4 >> 4) * 16384u;
        *(uint2 *)(smem + SM_WHI + off) = vh;
    }
    __syncthreads();

    float *spart = (float *)(smem + SM_SPART);
    int *snext = (int *)(smem + SM_NEXT);
    const float *b1s = (const float *)(smem + SM_B1);
    const float *w2s = (const float *)(smem + SM_W2);

    const int lr = lane >> 2, cq = lane & 3;
    const int bn = ng * 64 + ((lane >> 4) & 1) * 8 + (lane & 7);
    const int bkb = ((lane >> 3) & 1) * 8;
    const int prow0 = (tid * 2) >> 2, pc40 = (tid * 2) & 3;
    const int prow1 = (tid * 2 + 1) >> 2, pc41 = (tid * 2 + 1) & 3;
    const uint32_t abase = sb + SM_A + (uint32_t)(mg * 32 + lr) * 96u + (uint32_t)cq * 8u;

    auto load_stage = [&](size_t tr0, int ksv, int slot) {
        size_t gr0 = min(tr0 + prow0, (size_t)(NROWS - 1));
        size_t gr1 = min(tr0 + prow1, (size_t)(NROWS - 1));
        cp16(sb + SM_A + slot * A_STAGE + prow0 * 96 + pc40 * 16,
             x + gr0 * 256 + ksv * 16 + pc40 * 4);
        cp16(sb + SM_A + slot * A_STAGE + prow1 * 96 + pc41 * 16,
             x + gr1 * 256 + ksv * 16 + pc41 * 4);
        cp_commit();
    };

    int tile = blockIdx.x;
    if (tile < NTILES) {
        const size_t fr0 = (size_t)tile * TILE_M;
        load_stage(fr0, 0, 0);
        load_stage(fr0, 1, 1);
    }

    while (tile < NTILES) {
        const size_t r0 = (size_t)tile * TILE_M;
        // fetch next ticket early; published by mainloop-end barrier
        if (tid == 0) *snext = atomicAdd(&g_ticket, 1);

        float acc[2][8][4];
        #pragma unroll
        for (int mt = 0; mt < 2; mt++)
            #pragma unroll
            for (int nt = 0; nt < 8; nt++) {
                int c0 = ng * 64 + nt * 8 + cq * 2;
                acc[mt][nt][0] = b1s[c0];
                acc[mt][nt][1] = b1s[c0 + 1];
                acc[mt][nt][2] = acc[mt][nt][0];
                acc[mt][nt][3] = acc[mt][nt][1];
            }

        #pragma unroll
        for (int ks = 0; ks < 16; ks++) {
            if (ks < 15) cp_wait<1>(); else cp_wait<0>();
            __syncthreads();
            if (ks + 2 < 16) load_stage(r0, ks + 2, (ks + 2) % 3);

            const uint32_t aslot = abase + (uint32_t)((ks % 3) * A_STAGE);
            uint32_t ah[2][4];
            #pragma unroll
            for (int mt = 0; mt < 2; mt++)
                #pragma unroll
                for (int j = 0; j < 4; j++) {
                    float2 v;
                    uint32_t addr = aslot + (uint32_t)((mt * 16 + (j & 1) * 8) * 96 + (j >> 1) * 32);
                    asm volatile("ld.shared.v2.f32 {%0,%1}, [%2];"
                                 : "=f"(v.x), "=f"(v.y) : "r"(addr));
                    ah[mt][j] = packh(v.x, v.y);
                }
            uint32_t bh[4][4];
            const uint32_t whp = sb + SM_WHI + (uint32_t)(ks >> 2) * 16384u;
            const int ki = (ks & 3) * 16 + bkb;
            #pragma unroll
            for (int nt2 = 0; nt2 < 4; nt2++) {
                uint32_t off = SWZ((bn + nt2 * 16) * 128 + ki * 2);
                ldsm4(bh[nt2], whp + off);
            }
            #pragma unroll
            for (int mt = 0; mt < 2; mt++)
                #pragma unroll
                for (int nt = 0; nt < 8; nt++)
                    mma16816(acc[mt][nt], ah[mt], &bh[nt >> 1][(nt & 1) * 2]);
        }

        // ring reads done; next ticket visible -> prefetch next tile during epilogue
        __syncthreads();
        const int ntile = *snext;
        if (ntile < NTILES) {
            const size_t nr0 = (size_t)ntile * TILE_M;
            load_stage(nr0, 0, 0);
            load_stage(nr0, 1, 1);
        }

        // ---- epilogue: MUFU tanh + dot W2 ----
        #pragma unroll
        for (int mt = 0; mt < 2; mt++)
            #pragma unroll
            for (int qh = 0; qh < 2; qh++) {
                float p = 0.f;
                #pragma unroll
                for (int nt = 0; nt < 8; nt++) {
                    int c0 = ng * 64 + nt * 8 + cq * 2;
                    p += htanh(acc[mt][nt][qh * 2 + 0]) * w2s[c0] +
                         htanh(acc[mt][nt][qh * 2 + 1]) * w2s[c0 + 1];
                }
                p += __shfl_xor_sync(0xffffffffu, p, 1);
                p += __shfl_xor_sync(0xffffffffu, p, 2);
                if (cq == 0)
                    spart[(mg * 32 + mt * 16 + qh * 8 + lr) * 2 + ng] = p;
            }
        __syncthreads();
        if (tid < 128) {
            size_t row = r0 + tid;
            const bool valid = row < NROWS;
            const int g = batch[valid ? row : NROWS - 1];
            float sc = -3.4e38f;
            if (valid) {
                sc = spart[tid * 2] + spart[tid * 2 + 1];
                g_scores[row] = sc;
            }
            float v = sc;
            #pragma unroll
            for (int off = 1; off < 32; off <<= 1) {
                float vv = __shfl_down_sync(0xffffffffu, v, off);
                int gg = __shfl_down_sync(0xffffffffu, g, off);
                if ((tid & 31) + off < 32 && gg == g) v = fmaxf(v, vv);
            }
            int gprev = __shfl_up_sync(0xffffffffu, g, 1);
            if (valid && ((tid & 31) == 0 || gprev != g)) atomicMax(&g_maxu[g], fenc(v));
        }
        __syncthreads();
        tile = ntile;
    }
}

// ---------------- den: e=exp(s-max) in place + segmented atomicAdd + zero out ----------------
constexpr int RPB = 256;
constexpr int PBLK = (NROWS + RPB - 1) / RPB;  // 782

__global__ void __launch_bounds__(256)
den_kernel(const int *__restrict__ batch, float *__restrict__ out) {
    const int row = blockIdx.x * 256 + threadIdx.x;
    const int lane = threadIdx.x & 31;
    if (blockIdx.x < NSEG) out[(size_t)blockIdx.x * DIMX + threadIdx.x] = 0.0f;
    const bool valid = row < NROWS;
    const int g = batch[valid ? row : NROWS - 1];
    float e = 0.f;
    if (valid) {
        e = expf(g_scores[row] - fdec(g_maxu[g]));
        g_scores[row] = e;
    }
    float v = e;
    #pragma unroll
    for (int off = 1; off < 32; off <<= 1) {
        float vv = __shfl_down_sync(0xffffffffu, v, off);
        int gg = __shfl_down_sync(0xffffffffu, g, off);
        if (lane + off < 32 && gg == g) v += vv;
    }
    int gprev = __shfl_up_sync(0xffffffffu, g, 1);
    if ((lane == 0 || gprev != g) && v != 0.f) atomicAdd(&g_den[g], v);
}

// ---------------- pool2: float4 lanes, 4 row-groups, 8 rows in flight ----------------
__global__ void __launch_bounds__(256)
pool2_kernel(const float *__restrict__ x, const int *__restrict__ batch,
             float *__restrict__ out) {
    const int tid = threadIdx.x;
    const int rq = tid >> 6, cq = tid & 63;
    const int r0 = blockIdx.x * RPB;
    const int rend = min(r0 + RPB, NROWS);
    const int g0 = batch[r0], g1 = batch[rend - 1];
    __shared__ float4 red4[256];
    const float4 *x4 = (const float4 *)x;

    for (int g = g0; g <= g1; g++) {
        int lo = r0, hi = rend;
        while (lo < hi) { int mid = (lo + hi) >> 1; if (batch[mid] < g) lo = mid + 1; else hi = mid; }
        const int s = lo;
        lo = r0; hi = rend;
        while (lo < hi) { int mid = (lo + hi) >> 1; if (batch[mid] < g + 1) lo = mid + 1; else hi = mid; }
        const int e = lo;
        if (s < e) {
            float4 acc = make_float4(0.f, 0.f, 0.f, 0.f);
            int r = s + rq;
            // 8 rows in flight per thread: r, r+4, ..., r+28
            for (; r + 28 < e; r += 32) {
                float w0 = g_scores[r];       float4 v0 = x4[(size_t)r * 64 + cq];
                float w1 = g_scores[r + 4];   float4 v1 = x4[(size_t)(r + 4) * 64 + cq];
                float w2 = g_scores[r + 8];   float4 v2 = x4[(size_t)(r + 8) * 64 + cq];
                float w3 = g_scores[r + 12];  float4 v3 = x4[(size_t)(r + 12) * 64 + cq];
                float w4 = g_scores[r + 16];  float4 v4 = x4[(size_t)(r + 16) * 64 + cq];
                float w5 = g_scores[r + 20];  float4 v5 = x4[(size_t)(r + 20) * 64 + cq];
                float w6 = g_scores[r + 24];  float4 v6 = x4[(size_t)(r + 24) * 64 + cq];
                float w7 = g_scores[r + 28];  float4 v7 = x4[(size_t)(r + 28) * 64 + cq];
                acc.x = fmaf(w0, v0.x, acc.x); acc.y = fmaf(w0, v0.y, acc.y);
                acc.z = fmaf(w0, v0.z, acc.z); acc.w = fmaf(w0, v0.w, acc.w);
                acc.x = fmaf(w1, v1.x, acc.x); acc.y = fmaf(w1, v1.y, acc.y);
                acc.z = fmaf(w1, v1.z, acc.z); acc.w = fmaf(w1, v1.w, acc.w);
                acc.x = fmaf(w2, v2.x, acc.x); acc.y = fmaf(w2, v2.y, acc.y);
                acc.z = fmaf(w2, v2.z, acc.z); acc.w = fmaf(w2, v2.w, acc.w);
                acc.x = fmaf(w3, v3.x, acc.x); acc.y = fmaf(w3, v3.y, acc.y);
                acc.z = fmaf(w3, v3.z, acc.z); acc.w = fmaf(w3, v3.w, acc.w);
                acc.x = fmaf(w4, v4.x, acc.x); acc.y = fmaf(w4, v4.y, acc.y);
                acc.z = fmaf(w4, v4.z, acc.z); acc.w = fmaf(w4, v4.w, acc.w);
                acc.x = fmaf(w5, v5.x, acc.x); acc.y = fmaf(w5, v5.y, acc.y);
                acc.z = fmaf(w5, v5.z, acc.z); acc.w = fmaf(w5, v5.w, acc.w);
                acc.x = fmaf(w6, v6.x, acc.x); acc.y = fmaf(w6, v6.y, acc.y);
                acc.z = fmaf(w6, v6.z, acc.z); acc.w = fmaf(w6, v6.w, acc.w);
                acc.x = fmaf(w7, v7.x, acc.x); acc.y = fmaf(w7, v7.y, acc.y);
                acc.z = fmaf(w7, v7.z, acc.z); acc.w = fmaf(w7, v7.w, acc.w);
            }
            for (; r < e; r += 4) {
                float w0 = g_scores[r];
                float4 v0 = x4[(size_t)r * 64 + cq];
                acc.x = fmaf(w0, v0.x, acc.x); acc.y = fmaf(w0, v0.y, acc.y);
                acc.z = fmaf(w0, v0.z, acc.z); acc.w = fmaf(w0, v0.w, acc.w);
            }
            red4[tid] = acc;
            __syncthreads();
            if (rq == 0) {
                const float inv = 1.0f / g_den[g];
                float4 a = red4[tid], b = red4[tid + 64];
                float4 c = red4[tid + 128], d = red4[tid + 192];
                a.x += b.x + c.x + d.x; a.y += b.y + c.y + d.y;
                a.z += b.z + c.z + d.z; a.w += b.w + c.w + d.w;
                float *op = out + (size_t)g * DIMX + cq * 4;
                atomicAdd(op + 0, a.x * inv);
                atomicAdd(op + 1, a.y * inv);
                atomicAdd(op + 2, a.z * inv);
                atomicAdd(op + 3, a.w * inv);
            }
            __syncthreads();
        }
    }
}

// ---------------- launch ----------------
extern "C" void kernel_launch(void *const *d_in, const int *in_sizes, int n_in,
                              void *d_out, int out_size) {
    (void)in_sizes; (void)n_in; (void)out_size;
    const float *x = (const float *)d_in[0];
    const int *batch = (const int *)d_in[1];
    const float *W1 = (const float *)d_in[2];
    const float *b1 = (const float *)d_in[3];
    const float *W2 = (const float *)d_in[4];
    float *out = (float *)d_out;

    static int grid_s = 0;
    if (grid_s == 0) {
        int sm = 148;
        cudaDeviceGetAttribute(&sm, cudaDevAttrMultiProcessorCount, 0);
        grid_s = 2 * sm;
        cudaFuncSetAttribute(scores_kernel, cudaFuncAttributeMaxDynamicSharedMemorySize,
                             SMEM_TOTAL);
    }
    prep_w<<<HID * DIMX / 256, 256>>>(W1, grid_s);
    scores_kernel<<<grid_s, TPB, SMEM_TOTAL>>>(x, b1, W2, batch);
    den_kernel<<<PBLK, 256>>>(batch, out);
    pool2_kernel<<<PBLK, 256>>>(x, batch, out);
}